// round 1
// baseline (speedup 1.0000x reference)
#include <cuda_runtime.h>
#include <cuda_bf16.h>
#include <math.h>

// Problem constants
#define B_ROWS   16384
#define DIM      2048
#define OUT_CL   1000
#define N_INNER  255
#define N_LEAF   256

// ---------------- device scratch (no allocation allowed) ----------------
__device__ float  g_probs[(size_t)B_ROWS * 256];   // sigmoid(beta*(xW^T+b)), padded N=256
__device__ float  g_Q[(size_t)N_LEAF * OUT_CL];    // exp(log_softmax(leaf_params))
__device__ float  g_logQt[(size_t)OUT_CL * N_LEAF];// transposed log_softmax
__device__ float  g_leafSum[N_LEAF];               // sum over batch of leaf path probs
__device__ double g_lossSum;                       // sum over batch of dot(path, logQ[:,t])
__device__ int    g_t[B_ROWS];                     // target index per row
__device__ int    g_best[B_ROWS];                  // argmax leaf per row

// ---------------- init ----------------
__global__ void init_kernel() {
    int t = threadIdx.x;
    if (t < N_LEAF) g_leafSum[t] = 0.0f;
    if (t == 0) g_lossSum = 0.0;
}

// ---------------- log_softmax of leaf_params: Q and logQt ----------------
__global__ void softmax_kernel(const float* __restrict__ lp) {
    __shared__ float red[256];
    int r = blockIdx.x;            // 0..255 leaf row
    int tid = threadIdx.x;         // 256 threads
    const float* row = lp + (size_t)r * OUT_CL;

    float m = -INFINITY;
    for (int j = tid; j < OUT_CL; j += 256) m = fmaxf(m, row[j]);
    red[tid] = m; __syncthreads();
    for (int s = 128; s; s >>= 1) { if (tid < s) red[tid] = fmaxf(red[tid], red[tid + s]); __syncthreads(); }
    float rowmax = red[0];
    __syncthreads();

    float sum = 0.0f;
    for (int j = tid; j < OUT_CL; j += 256) sum += expf(row[j] - rowmax);
    red[tid] = sum; __syncthreads();
    for (int s = 128; s; s >>= 1) { if (tid < s) red[tid] += red[tid + s]; __syncthreads(); }
    float lse = rowmax + logf(red[0]);

    for (int j = tid; j < OUT_CL; j += 256) {
        float lq = row[j] - lse;
        g_Q[(size_t)r * OUT_CL + j] = expf(lq);
        g_logQt[(size_t)j * N_LEAF + r] = lq;
    }
}

// ---------------- target extraction from one-hot y ----------------
__global__ void target_kernel(const float* __restrict__ y) {
    int warp = threadIdx.x >> 5, lane = threadIdx.x & 31;
    int gw = blockIdx.x * (blockDim.x >> 5) + warp;
    int nw = gridDim.x * (blockDim.x >> 5);
    for (int b = gw; b < B_ROWS; b += nw) {
        const float* row = y + (size_t)b * OUT_CL;
        float bv = -INFINITY; int bi = 0;
        for (int j = lane; j < OUT_CL; j += 32) {
            float v = row[j];
            if (v > bv) { bv = v; bi = j; }
        }
        for (int off = 16; off; off >>= 1) {
            float ov = __shfl_down_sync(0xffffffffu, bv, off);
            int   oi = __shfl_down_sync(0xffffffffu, bi, off);
            if (ov > bv || (ov == bv && oi < bi)) { bv = ov; bi = oi; }
        }
        if (lane == 0) g_t[b] = bi;
    }
}

// ---------------- fp32 GEMM: probs = sigmoid(beta*(x@W^T + b)) ----------------
// 128x128x16 tile, 256 threads, 8x8 per thread.
__global__ __launch_bounds__(256, 2)
void gemm_probs_kernel(const float* __restrict__ X, const float* __restrict__ W,
                       const float* __restrict__ bias, const float* __restrict__ beta) {
    __shared__ float As[16][128];
    __shared__ float Bs[16][128];
    const int mBase = blockIdx.x * 128;
    const int nBase = blockIdx.y * 128;
    const int tid = threadIdx.x;
    const int ty = tid >> 4, tx = tid & 15;

    float acc[8][8];
    #pragma unroll
    for (int i = 0; i < 8; i++)
        #pragma unroll
        for (int j = 0; j < 8; j++) acc[i][j] = 0.0f;

    for (int k0 = 0; k0 < DIM; k0 += 16) {
        #pragma unroll
        for (int i = 0; i < 2; i++) {
            int f = tid + i * 256;          // 0..511 float4 slot
            int row = f >> 2;
            int kq = (f & 3) << 2;
            float4 v = *(const float4*)(X + (size_t)(mBase + row) * DIM + k0 + kq);
            As[kq + 0][row] = v.x; As[kq + 1][row] = v.y;
            As[kq + 2][row] = v.z; As[kq + 3][row] = v.w;
        }
        #pragma unroll
        for (int i = 0; i < 2; i++) {
            int f = tid + i * 256;
            int row = f >> 2;
            int kq = (f & 3) << 2;
            int n = nBase + row;
            float4 v = make_float4(0.f, 0.f, 0.f, 0.f);
            if (n < N_INNER) v = *(const float4*)(W + (size_t)n * DIM + k0 + kq);
            Bs[kq + 0][row] = v.x; Bs[kq + 1][row] = v.y;
            Bs[kq + 2][row] = v.z; Bs[kq + 3][row] = v.w;
        }
        __syncthreads();
        #pragma unroll
        for (int k = 0; k < 16; k++) {
            float4 a0 = *(const float4*)&As[k][ty * 8];
            float4 a1 = *(const float4*)&As[k][ty * 8 + 4];
            float4 b0 = *(const float4*)&Bs[k][tx * 8];
            float4 b1 = *(const float4*)&Bs[k][tx * 8 + 4];
            float ra[8] = {a0.x, a0.y, a0.z, a0.w, a1.x, a1.y, a1.z, a1.w};
            float rb[8] = {b0.x, b0.y, b0.z, b0.w, b1.x, b1.y, b1.z, b1.w};
            #pragma unroll
            for (int i = 0; i < 8; i++)
                #pragma unroll
                for (int j = 0; j < 8; j++) acc[i][j] = fmaf(ra[i], rb[j], acc[i][j]);
        }
        __syncthreads();
    }

    #pragma unroll
    for (int i = 0; i < 8; i++) {
        int m = mBase + ty * 8 + i;
        #pragma unroll
        for (int j = 0; j < 8; j++) {
            int n = nBase + tx * 8 + j;
            float v = 0.0f;
            if (n < N_INNER) {
                float z = beta[n] * (acc[i][j] + bias[n]);
                v = 1.0f / (1.0f + expf(-z));
            }
            g_probs[(size_t)m * 256 + n] = v;
        }
    }
}

// ---------------- tree expansion: leaf paths, loss dot, argmax, leaf sums ----------------
// one warp per row; lane owns leaves [lane*8, lane*8+8)
__global__ __launch_bounds__(256)
void path_kernel() {
    __shared__ float sp[8][256];
    __shared__ float red[256];
    const int warp = threadIdx.x >> 5, lane = threadIdx.x & 31;
    const int gw = blockIdx.x * 8 + warp;
    const int nw = gridDim.x * 8;
    const int base = lane * 8;

    float lacc[8];
    #pragma unroll
    for (int k = 0; k < 8; k++) lacc[k] = 0.0f;
    float dacc = 0.0f;

    for (int b = gw; b < B_ROWS; b += nw) {
        const float* pr = g_probs + (size_t)b * 256;
        for (int i = lane; i < 256; i += 32) sp[warp][i] = pr[i];
        __syncwarp();

        // shared prefix for depths 1..5 (identical for all 8 leaves of this lane)
        float pre = 1.0f;
        #pragma unroll
        for (int d = 1; d <= 5; d++) {
            int g = (1 << (d - 1)) - 1 + (base >> (9 - d));
            int bit = (base >> (8 - d)) & 1;
            float pv = sp[warp][g];
            pre *= bit ? pv : (1.0f - pv);
        }
        float leaf[8];
        #pragma unroll
        for (int k = 0; k < 8; k++) {
            int l = base + k;
            float f = pre;
            #pragma unroll
            for (int d = 6; d <= 8; d++) {
                int g = (1 << (d - 1)) - 1 + (l >> (9 - d));
                int bit = (l >> (8 - d)) & 1;
                float pv = sp[warp][g];
                f *= bit ? pv : (1.0f - pv);
            }
            leaf[k] = f;
            lacc[k] += f;
        }

        // loss dot with logQt[target]
        int t = g_t[b];
        const float* lq = g_logQt + (size_t)t * 256 + base;
        float dl = 0.0f;
        #pragma unroll
        for (int k = 0; k < 8; k++) dl += leaf[k] * lq[k];
        dacc += dl;

        // argmax (first max wins on ties)
        float bv = leaf[0]; int bi = base;
        #pragma unroll
        for (int k = 1; k < 8; k++) if (leaf[k] > bv) { bv = leaf[k]; bi = base + k; }
        for (int off = 16; off; off >>= 1) {
            float ov = __shfl_down_sync(0xffffffffu, bv, off);
            int   oi = __shfl_down_sync(0xffffffffu, bi, off);
            if (ov > bv || (ov == bv && oi < bi)) { bv = ov; bi = oi; }
        }
        if (lane == 0) g_best[b] = bi;
        __syncwarp();
    }

    #pragma unroll
    for (int k = 0; k < 8; k++) atomicAdd(&g_leafSum[base + k], lacc[k]);

    red[threadIdx.x] = dacc;
    __syncthreads();
    for (int s = 128; s; s >>= 1) { if (threadIdx.x < s) red[threadIdx.x] += red[threadIdx.x + s]; __syncthreads(); }
    if (threadIdx.x == 0) atomicAdd(&g_lossSum, (double)red[0]);
}

// ---------------- finalize: build node sums, alpha, C, loss ----------------
__global__ void final_kernel(float* __restrict__ out, int writeLoss) {
    if (threadIdx.x != 0 || blockIdx.x != 0) return;
    float S[255];
    for (int j = 0; j < 128; j++) S[127 + j] = g_leafSum[2 * j] + g_leafSum[2 * j + 1];
    for (int g = 126; g >= 0; g--) S[g] = S[2 * g + 1] + S[2 * g + 2];

    float C = 0.0f;
    int idx = 0;
    for (int d = 1; d <= 7; d++) {
        int n = 1 << (d - 1);
        float lm = 0.1f * exp2f((float)(-d)) * 0.5f;
        for (int j = 0; j < n; j++) {
            int g = idx + j;
            float denom = S[g];
            if (denom == 0.0f) denom = 1e-6f;
            float a = S[2 * g + 2] / denom;
            a = fminf(fmaxf(a, 1e-6f), 1.0f - 1e-6f);
            C -= lm * (logf(a) + log1pf(-a));
        }
        idx += n;
    }
    double lt = g_lossSum / (double)B_ROWS;
    if (writeLoss) out[0] = (float)(-lt + (double)C);
}

// ---------------- output gather: out[b,:] = Q[best[b],:] ----------------
__global__ void gather_kernel(float* __restrict__ out) {
    for (int b = blockIdx.x; b < B_ROWS; b += gridDim.x) {
        const float* q = g_Q + (size_t)g_best[b] * OUT_CL;
        float* o = out + (size_t)b * OUT_CL;
        for (int j = threadIdx.x; j < OUT_CL; j += blockDim.x) o[j] = q[j];
    }
}

extern "C" void kernel_launch(void* const* d_in, const int* in_sizes, int n_in,
                              void* d_out, int out_size) {
    const float* x    = (const float*)d_in[0];
    const float* y    = (const float*)d_in[1];
    const float* W    = (const float*)d_in[2];
    const float* bias = (const float*)d_in[3];
    const float* beta = (const float*)d_in[4];
    const float* lp   = (const float*)d_in[5];
    float* out = (float*)d_out;

    // (loss, output) flattened: loss first if there is room for it.
    int hasLoss = (out_size >= B_ROWS * OUT_CL + 1) ? 1 : 0;
    float* outRows = out + hasLoss;

    init_kernel<<<1, 256>>>();
    softmax_kernel<<<N_LEAF, 256>>>(lp);
    target_kernel<<<256, 256>>>(y);
    gemm_probs_kernel<<<dim3(B_ROWS / 128, 2), 256>>>(x, W, bias, beta);
    path_kernel<<<256, 256>>>();
    final_kernel<<<1, 32>>>(out, hasLoss);
    gather_kernel<<<2048, 256>>>(outRows);
}